// round 17
// baseline (speedup 1.0000x reference)
#include <cuda_runtime.h>
#include <cuda_bf16.h>
#include <cstdint>

#define BB   64
#define CC   256
#define NTOK 1600
#define VQ   25
#define HH   8
#define HD   32
#define RR   200
#define RP   256
#define KSPL 5        // gemm2 split-K factor
#define K2   2048     // final_mma K = HH*CC

typedef __nv_bfloat16 bf;

// -------- device scratch (allocation-free rule; zero-init at load) --------
__device__ __align__(16) bf    g_Qeh[BB * RP * CC];   // pad rows 200..255 stay 0
__device__ __align__(16) bf    g_Qel[BB * RP * CC];
__device__ __align__(16) bf    g_Xh [BB * CC * NTOK];
__device__ __align__(16) bf    g_Xl [BB * CC * NTOK];
__device__ __align__(16) bf    g_Ph [BB * RP * NTOK]; // pad rows stay 0
__device__ __align__(16) bf    g_Pl [BB * RP * NTOK];
__device__ __align__(16) float g_S  [BB * RP * NTOK];
__device__ __align__(16) float g_Yp [KSPL * BB * RP * CC];  // split-K partials
__device__ __align__(16) bf    g_Y2h[BB * 32 * K2];   // Y transposed; pad v rows stay 0
__device__ __align__(16) bf    g_Y2l[BB * 32 * K2];
__device__ __align__(16) bf    g_We2h[CC * K2];       // folded proj@v weights
__device__ __align__(16) bf    g_We2l[CC * K2];
__device__ int g_ready[BB];                            // per-b producer counter

// ==================== PTX helpers (baseline ISA only) ====================
__device__ __forceinline__ uint32_t smem_u32(const void* p) {
    uint32_t a;
    asm("{ .reg .u64 t; cvta.to.shared.u64 t, %1; cvt.u32.u64 %0, t; }" : "=r"(a) : "l"(p));
    return a;
}
__device__ __forceinline__ void ldsm4(uint32_t* r, uint32_t a) {
    asm volatile("ldmatrix.sync.aligned.m8n8.x4.shared.b16 {%0,%1,%2,%3}, [%4];"
                 : "=r"(r[0]), "=r"(r[1]), "=r"(r[2]), "=r"(r[3]) : "r"(a));
}
__device__ __forceinline__ void ldsm4t(uint32_t* r, uint32_t a) {
    asm volatile("ldmatrix.sync.aligned.m8n8.x4.trans.shared.b16 {%0,%1,%2,%3}, [%4];"
                 : "=r"(r[0]), "=r"(r[1]), "=r"(r[2]), "=r"(r[3]) : "r"(a));
}
__device__ __forceinline__ void mma_bf16(float* c, const uint32_t* a, const uint32_t* b) {
    asm volatile("mma.sync.aligned.m16n8k16.row.col.f32.bf16.bf16.f32 "
                 "{%0,%1,%2,%3}, {%4,%5,%6,%7}, {%8,%9}, {%0,%1,%2,%3};"
                 : "+f"(c[0]), "+f"(c[1]), "+f"(c[2]), "+f"(c[3])
                 : "r"(a[0]), "r"(a[1]), "r"(a[2]), "r"(a[3]), "r"(b[0]), "r"(b[1]));
}
__device__ __forceinline__ void cp16(uint32_t d, const void* g) {
    asm volatile("cp.async.cg.shared.global [%0], [%1], 16;" :: "r"(d), "l"(g) : "memory");
}
#define CP_COMMIT() asm volatile("cp.async.commit_group;" ::: "memory")
#define CP_WAIT(n)  asm volatile("cp.async.wait_group %0;" :: "n"(n) : "memory")

__device__ __forceinline__ void split_bf(float v, bf& h, bf& l) {
    h = __float2bfloat16(v);
    l = __float2bfloat16(v - __bfloat162float(h));
}
// RELEASE: every thread fences its own writes; syncthreads guarantees all
// fences in the block executed before thread 0's atomicAdd (pairs with the
// consumer's ld.acquire). The missing __syncthreads was the R16 race.
__device__ __forceinline__ void publish(int b) {
    __threadfence();
    __syncthreads();
    if (threadIdx.x == 0) atomicAdd(&g_ready[b], 1);
}

// ==================== mega1: weff | qeff | convx | gemm1 (spin-ordered) ==========
// bid 0..63: weff. Then per b (451 blocks): [qeff(1), convx(400), gemm1(50)].
// gemm1 blocks acquire-spin until g_ready[b] == 401.
#define B1P  144
#define STG1 (32768 + 2 * 64 * B1P)    // 51200
#define NPB  451

__global__ __launch_bounds__(256, 2)
void mega1(const float* __restrict__ x_cls, const float* __restrict__ qw,
           const float* __restrict__ kw, const float* __restrict__ temp,
           const float* __restrict__ pw, const float* __restrict__ vw,
           const float* __restrict__ xp) {
    extern __shared__ char smem[];
    const int bx = blockIdx.x, tid = threadIdx.x;

    if (bx < BB) {
        // ---- weff: We2[co][h*256+c], bf16 split ----
        const int h = bx >> 3, co0 = (bx & 7) * 32, c = tid;
        float vv[HD];
#pragma unroll
        for (int d = 0; d < HD; d++) vv[d] = vw[(h * HD + d) * CC + c];
        for (int i = 0; i < 32; i++) {
            const int co = co0 + i;
            float a = 0.f;
#pragma unroll
            for (int d = 0; d < HD; d++) a += pw[co * CC + h * HD + d] * vv[d];
            bf hi, lo; split_bf(a, hi, lo);
            const long long o = (long long)co * K2 + h * CC + c;
            g_We2h[o] = hi;
            g_We2l[o] = lo;
        }
        return;
    }

    const int rel = bx - BB;
    const int b = rel / NPB, role = rel % NPB;

    if (role == 0) {
        // ---- qeff (dynamic smem) ----
        float* buf = (float*)smem;
        for (int i = tid; i < CC * VQ; i += 256) buf[i] = x_cls[b * CC * VQ + i];
        __syncthreads();

        float acc[VQ];
#pragma unroll
        for (int v = 0; v < VQ; v++) acc[v] = 0.f;
        const float* wrow = qw + tid * CC;
        for (int c2 = 0; c2 < CC; c2++) {
            float w = wrow[c2];
#pragma unroll
            for (int v = 0; v < VQ; v++) acc[v] += w * buf[c2 * VQ + v];
        }
        const float s = temp[tid >> 5] * 0.17677669529663687f;
        __syncthreads();
#pragma unroll
        for (int v = 0; v < VQ; v++) buf[v * 260 + tid] = acc[v] * s;
        __syncthreads();

        for (int h = 0; h < HH; h++) {
            float kv[HD];
#pragma unroll
            for (int d = 0; d < HD; d++) kv[d] = kw[(h * HD + d) * CC + tid];
            for (int v = 0; v < VQ; v++) {
                float a = 0.f;
#pragma unroll
                for (int d = 0; d < HD; d++) a += buf[v * 260 + h * HD + d] * kv[d];
                bf hi, lo; split_bf(a, hi, lo);
                const long long idx = ((long long)b * RP + h * VQ + v) * CC + tid;
                g_Qeh[idx] = hi;
                g_Qel[idx] = lo;
            }
        }
        publish(b);
        return;
    }

    if (role <= 400) {
        // ---- convx slice: 1024 elements of batch b ----
        const long long i = (long long)b * (CC * NTOK) + (long long)(role - 1) * 1024 + tid * 4;
        float4 v = *(const float4*)(xp + i);
        bf h0, l0, h1, l1, h2, l2, h3, l3;
        split_bf(v.x, h0, l0); split_bf(v.y, h1, l1);
        split_bf(v.z, h2, l2); split_bf(v.w, h3, l3);
        __nv_bfloat162* ph = (__nv_bfloat162*)(g_Xh + i);
        __nv_bfloat162* pl = (__nv_bfloat162*)(g_Xl + i);
        ph[0] = __nv_bfloat162(h0, h1); ph[1] = __nv_bfloat162(h2, h3);
        pl[0] = __nv_bfloat162(l0, l1); pl[1] = __nv_bfloat162(l2, l3);
        publish(b);
        return;
    }

    // ---- gemm1 block: S[b][r][n] = Qe @ X ----
    {
        const int g = role - 401;           // 0..49
        const int n0 = (g % 25) * 64;
        const int r0 = (g / 25) * 128;

        // acquire-spin until this batch's Qe and X split are published
        if (tid == 0) {
            int v;
            do {
                asm volatile("ld.acquire.gpu.global.s32 %0, [%1];"
                             : "=r"(v) : "l"(&g_ready[b]));
            } while (v < 401);
        }
        __syncthreads();

        constexpr int A_HI = 0, A_LO = 16384, B_HI = 32768, B_LO = 32768 + 64 * B1P;
        const int lane = tid & 31, wid = tid >> 5;
        const int wm = wid >> 1, wn = wid & 1;
        const uint32_t sb = smem_u32(smem);

        float acc[2][4][4];
#pragma unroll
        for (int i = 0; i < 2; i++)
#pragma unroll
            for (int j = 0; j < 4; j++)
#pragma unroll
                for (int k = 0; k < 4; k++) acc[i][j][k] = 0.f;

        const bf* Ah = g_Qeh + ((long long)b * RP + r0) * CC;
        const bf* Al = g_Qel + ((long long)b * RP + r0) * CC;
        const bf* Bh = g_Xh + (long long)b * CC * NTOK + n0;
        const bf* Bl = g_Xl + (long long)b * CC * NTOK + n0;

        auto load = [&](int kc, int st) {
            const uint32_t base = sb + st * STG1;
#pragma unroll
            for (int it = 0; it < 4; it++) {
                int idx = tid + it * 256;
                int r = idx >> 3, c = idx & 7;
                uint32_t off = (uint32_t)(r * 128 + c * 16);
                off ^= (off >> 3) & 0x70;
                const long long go = (long long)r * CC + kc * 64 + c * 8;
                cp16(base + A_HI + off, Ah + go);
                cp16(base + A_LO + off, Al + go);
            }
#pragma unroll
            for (int it = 0; it < 2; it++) {
                int idx = tid + it * 256;
                int r = idx >> 3, c8 = idx & 7;
                const long long go = (long long)(kc * 64 + r) * NTOK + c8 * 8;
                cp16(base + B_HI + r * B1P + c8 * 16, Bh + go);
                cp16(base + B_LO + r * B1P + c8 * 16, Bl + go);
            }
        };

        load(0, 0);
        CP_COMMIT();

        for (int kc = 0; kc < 4; kc++) {
            if (kc + 1 < 4) {
                load(kc + 1, (kc + 1) & 1);
                CP_COMMIT();
                CP_WAIT(1);
            } else {
                CP_WAIT(0);
            }
            __syncthreads();

            const uint32_t base = sb + (kc & 1) * STG1;
#pragma unroll
            for (int ks = 0; ks < 4; ks++) {
                uint32_t ah[2][4], al[2][4], bh[4][2], bl[4][2];
                const uint32_t kbyte = ks * 32 + (lane >> 4) * 16;
#pragma unroll
                for (int mf = 0; mf < 2; mf++) {
                    uint32_t row = wm * 32 + mf * 16 + (lane & 15);
                    uint32_t off = row * 128 + kbyte;
                    off ^= (off >> 3) & 0x70;
                    ldsm4(ah[mf], base + A_HI + off);
                    ldsm4(al[mf], base + A_LO + off);
                }
#pragma unroll
                for (int nf2 = 0; nf2 < 2; nf2++) {
                    uint32_t off = (ks * 16 + (lane & 15)) * B1P
                                 + (wn * 32 + nf2 * 16) * 2 + (lane >> 4) * 16;
                    uint32_t t[4];
                    ldsm4t(t, base + B_HI + off);
                    bh[2 * nf2][0] = t[0]; bh[2 * nf2][1] = t[1];
                    bh[2 * nf2 + 1][0] = t[2]; bh[2 * nf2 + 1][1] = t[3];
                    ldsm4t(t, base + B_LO + off);
                    bl[2 * nf2][0] = t[0]; bl[2 * nf2][1] = t[1];
                    bl[2 * nf2 + 1][0] = t[2]; bl[2 * nf2 + 1][1] = t[3];
                }
#pragma unroll
                for (int mf = 0; mf < 2; mf++)
#pragma unroll
                    for (int nf = 0; nf < 4; nf++) mma_bf16(acc[mf][nf], ah[mf], bh[nf]);
#pragma unroll
                for (int mf = 0; mf < 2; mf++)
#pragma unroll
                    for (int nf = 0; nf < 4; nf++) mma_bf16(acc[mf][nf], ah[mf], bl[nf]);
#pragma unroll
                for (int mf = 0; mf < 2; mf++)
#pragma unroll
                    for (int nf = 0; nf < 4; nf++) mma_bf16(acc[mf][nf], al[mf], bh[nf]);
            }
            __syncthreads();
        }

        float* Out = g_S + ((long long)b * RP) * NTOK + n0 + wn * 32;
        const int rr = lane >> 2, cc2 = (lane & 3) * 2;
#pragma unroll
        for (int mf = 0; mf < 2; mf++)
#pragma unroll
            for (int nf = 0; nf < 4; nf++) {
                const int arow = r0 + wm * 32 + mf * 16 + rr;
                float* o = Out + (long long)arow * NTOK + nf * 8 + cc2;
                if (arow < RR)
                    *(float2*)o = make_float2(acc[mf][nf][0], acc[mf][nf][1]);
                if (arow + 8 < RR)
                    *(float2*)(o + 8LL * NTOK) = make_float2(acc[mf][nf][2], acc[mf][nf][3]);
            }
    }
}

// ==================== GEMM2: Yp[p][b][r][c] = P @ X^T over k-slice p ====================
#define STG2 49152
__global__ __launch_bounds__(256, 2)
void gemm2_mma() {
    extern __shared__ char smem[];
    constexpr int A_HI = 0, A_LO = 16384, B_HI = 32768, B_LO = 40960;
    const int b = blockIdx.z, c0 = blockIdx.x * 64;
    const int p = blockIdx.y >> 1, r0 = (blockIdx.y & 1) * 128;
    const int tid = threadIdx.x, lane = tid & 31, wid = tid >> 5;
    const int wm = wid >> 1, wn = wid & 1;
    const uint32_t sb = smem_u32(smem);

    float acc[2][4][4];
#pragma unroll
    for (int i = 0; i < 2; i++)
#pragma unroll
        for (int j = 0; j < 4; j++)
#pragma unroll
            for (int k = 0; k < 4; k++) acc[i][j][k] = 0.f;

    const bf* Ah = g_Ph + ((long long)b * RP + r0) * NTOK;
    const bf* Al = g_Pl + ((long long)b * RP + r0) * NTOK;
    const bf* Bh = g_Xh + ((long long)b * CC + c0) * NTOK;
    const bf* Bl = g_Xl + ((long long)b * CC + c0) * NTOK;

    auto load = [&](int kc, int st) {
        const uint32_t base = sb + st * STG2;
#pragma unroll
        for (int it = 0; it < 4; it++) {
            int idx = tid + it * 256;
            int r = idx >> 3, c = idx & 7;
            uint32_t off = (uint32_t)(r * 128 + c * 16);
            off ^= (off >> 3) & 0x70;
            const long long ga = (long long)r * NTOK + kc * 64 + c * 8;
            cp16(base + A_HI + off, Ah + ga);
            cp16(base + A_LO + off, Al + ga);
        }
#pragma unroll
        for (int it = 0; it < 2; it++) {
            int idx = tid + it * 256;
            int r = idx >> 3, c = idx & 7;
            uint32_t off = (uint32_t)(r * 128 + c * 16);
            off ^= (off >> 3) & 0x70;
            const long long gb = (long long)r * NTOK + kc * 64 + c * 8;
            cp16(base + B_HI + off, Bh + gb);
            cp16(base + B_LO + off, Bl + gb);
        }
    };

    load(p * KSPL, 0);
    CP_COMMIT();

    for (int j = 0; j < KSPL; j++) {
        if (j + 1 < KSPL) {
            load(p * KSPL + j + 1, (j + 1) & 1);
            CP_COMMIT();
            CP_WAIT(1);
        } else {
            CP_WAIT(0);
        }
        __syncthreads();

        const uint32_t base = sb + (j & 1) * STG2;
#pragma unroll
        for (int ks = 0; ks < 4; ks++) {
            uint32_t ah[2][4], al[2][4], bh[4][2], bl[4][2];
            const uint32_t kbyte = ks * 32 + (lane >> 4) * 16;
#pragma unroll
            for (int mf = 0; mf < 2; mf++) {
                uint32_t row = wm * 32 + mf * 16 + (lane & 15);
                uint32_t off = row * 128 + kbyte;
                off ^= (off >> 3) & 0x70;
                ldsm4(ah[mf], base + A_HI + off);
                ldsm4(al[mf], base + A_LO + off);
            }
#pragma unroll
            for (int nf2 = 0; nf2 < 2; nf2++) {
                uint32_t row = wn * 32 + nf2 * 16 + (lane >> 4) * 8 + (lane & 7);
                uint32_t kb = ks * 32 + ((lane >> 3) & 1) * 16;
                uint32_t off = row * 128 + kb;
                off ^= (off >> 3) & 0x70;
                uint32_t t[4];
                ldsm4(t, base + B_HI + off);
                bh[2 * nf2][0] = t[0]; bh[2 * nf2][1] = t[1];
                bh[2 * nf2 + 1][0] = t[2]; bh[2 * nf2 + 1][1] = t[3];
                ldsm4(t, base + B_LO + off);
                bl[2 * nf2][0] = t[0]; bl[2 * nf2][1] = t[1];
                bl[2 * nf2 + 1][0] = t[2]; bl[2 * nf2 + 1][1] = t[3];
            }
#pragma unroll
            for (int mf = 0; mf < 2; mf++)
#pragma unroll
                for (int nf = 0; nf < 4; nf++) mma_bf16(acc[mf][nf], ah[mf], bh[nf]);
#pragma unroll
            for (int mf = 0; mf < 2; mf++)
#pragma unroll
                for (int nf = 0; nf < 4; nf++) mma_bf16(acc[mf][nf], ah[mf], bl[nf]);
#pragma unroll
            for (int mf = 0; mf < 2; mf++)
#pragma unroll
                for (int nf = 0; nf < 4; nf++) mma_bf16(acc[mf][nf], al[mf], bh[nf]);
        }
        __syncthreads();
    }

    float* Out = g_Yp + (long long)p * (BB * RP * CC)
               + ((long long)b * RP) * CC + c0 + wn * 32;
    const int rr = lane >> 2, cc2 = (lane & 3) * 2;
#pragma unroll
    for (int mf = 0; mf < 2; mf++)
#pragma unroll
        for (int nf = 0; nf < 4; nf++) {
            const int arow = r0 + wm * 32 + mf * 16 + rr;
            float* o = Out + (long long)arow * CC + nf * 8 + cc2;
            if (arow < RR)
                *(float2*)o = make_float2(acc[mf][nf][0], acc[mf][nf][1]);
            if (arow + 8 < RR)
                *(float2*)(o + 8LL * CC) = make_float2(acc[mf][nf][2], acc[mf][nf][3]);
        }
}

// ==================== reduce_yt: sum split-K partials -> transposed bf16 Y2 ==========
__global__ __launch_bounds__(256)
void reduce_yt() {
    const int hv = blockIdx.x, b = blockIdx.y, c = threadIdx.x;
    const int h = hv / VQ, v = hv % VQ;
    const long long src = ((long long)b * RP + hv) * CC + c;
    float s = g_Yp[src];
#pragma unroll
    for (int p = 1; p < KSPL; p++) s += g_Yp[(long long)p * (BB * RP * CC) + src];
    bf hi, lo; split_bf(s, hi, lo);
    const long long dst = ((long long)b * 32 + v) * K2 + h * CC + c;
    g_Y2h[dst] = hi;
    g_Y2l[dst] = lo;
}

// ==================== final_mma: out[b] = We2 @ Y2[b]^T + bias; resets g_ready ======
#define STGF 40960
__global__ __launch_bounds__(256, 2)
void final_mma(const float* __restrict__ pb, float* __restrict__ out) {
    extern __shared__ char smem[];
    constexpr int A_HI = 0, A_LO = 16384, B_HI = 32768, B_LO = 36864;
    const int b = blockIdx.z, co0 = blockIdx.x * 128;
    const int tid = threadIdx.x, lane = tid & 31, wid = tid >> 5;
    const int wm = wid >> 1, wn = wid & 1;
    const uint32_t sb = smem_u32(smem);

    // reset producer counters for the next graph replay (stream-ordered)
    if (blockIdx.x == 0 && blockIdx.z == 0 && tid < BB) g_ready[tid] = 0;

    float acc[2][2][4];
#pragma unroll
    for (int i = 0; i < 2; i++)
#pragma unroll
        for (int j = 0; j < 2; j++)
#pragma unroll
            for (int k = 0; k < 4; k++) acc[i][j][k] = 0.f;

    const bf* Ah = g_We2h + (long long)co0 * K2;
    const bf* Al = g_We2l + (long long)co0 * K2;
    const bf* Bh = g_Y2h + (long long)b * 32 * K2;
    const bf* Bl = g_Y2l + (long long)b * 32 * K2;

    auto load = [&](int kc, int st) {
        const uint32_t base = sb + st * STGF;
#pragma unroll
        for (int it = 0; it < 4; it++) {
            int idx = tid + it * 256;
            int r = idx >> 3, c = idx & 7;
            uint32_t off = (uint32_t)(r * 128 + c * 16);
            off ^= (off >> 3) & 0x70;
            const long long ga = (long long)r * K2 + kc * 64 + c * 8;
            cp16(base + A_HI + off, Ah + ga);
            cp16(base + A_LO + off, Al + ga);
        }
        {
            int r = tid >> 3, c = tid & 7;
            uint32_t off = (uint32_t)(r * 128 + c * 16);
            off ^= (off >> 3) & 0x70;
            const long long gb = (long long)r * K2 + kc * 64 + c * 8;
            cp16(base + B_HI + off, Bh + gb);
            cp16(base + B_LO + off, Bl + gb);
        }
    };

    load(0, 0);
    CP_COMMIT();

    for (int kc = 0; kc < K2 / 64; kc++) {
        if (kc + 1 < K2 / 64) {
            load(kc + 1, (kc + 1) & 1);
            CP_COMMIT();
            CP_WAIT(1);
        } else {
            CP_WAIT(0);
        }
        __syncthreads();

        const uint32_t base = sb + (kc & 1) * STGF;
#pragma unroll
        for (int ks = 0; ks < 4; ks++) {
            uint32_t ah[2][4], al[2][4], bh[2][2], bl[2][2];
            const uint32_t kbyte = ks * 32 + (lane >> 4) * 16;
#pragma unroll
            for (int mf = 0; mf < 2; mf++) {
                uint32_t row = wm * 32 + mf * 16 + (lane & 15);
                uint32_t off = row * 128 + kbyte;
                off ^= (off >> 3) & 0x70;
                ldsm4(ah[mf], base + A_HI + off);
                ldsm4(al[mf], base + A_LO + off);
            }
            {
                uint32_t row = wn * 16 + (lane >> 4) * 8 + (lane & 7);
                uint32_t kb = ks * 32 + ((lane >> 3) & 1) * 16;
                uint32_t off = row * 128 + kb;
                off ^= (off >> 3) & 0x70;
                uint32_t t[4];
                ldsm4(t, base + B_HI + off);
                bh[0][0] = t[0]; bh[0][1] = t[1];
                bh[1][0] = t[2]; bh[1][1] = t[3];
                ldsm4(t, base + B_LO + off);
                bl[0][0] = t[0]; bl[0][1] = t[1];
                bl[1][0] = t[2]; bl[1][1] = t[3];
            }
#pragma unroll
            for (int mf = 0; mf < 2; mf++)
#pragma unroll
                for (int nf = 0; nf < 2; nf++) mma_bf16(acc[mf][nf], ah[mf], bh[nf]);
#pragma unroll
            for (int mf = 0; mf < 2; mf++)
#pragma unroll
                for (int nf = 0; nf < 2; nf++) mma_bf16(acc[mf][nf], ah[mf], bl[nf]);
#pragma unroll
            for (int mf = 0; mf < 2; mf++)
#pragma unroll
                for (int nf = 0; nf < 2; nf++) mma_bf16(acc[mf][nf], al[mf], bh[nf]);
        }
        __syncthreads();
    }

    const int rr = lane >> 2, cc2 = (lane & 3) * 2;
    float* ob = out + (long long)b * (CC * VQ);
#pragma unroll
    for (int mf = 0; mf < 2; mf++) {
        const int row0 = co0 + wm * 32 + mf * 16 + rr;
        const float b0 = pb[row0], b1 = pb[row0 + 8];
#pragma unroll
        for (int nf = 0; nf < 2; nf++) {
            const int v0 = wn * 16 + nf * 8 + cc2;
            if (v0 < VQ)     ob[row0 * VQ + v0]           = acc[mf][nf][0] + b0;
            if (v0 + 1 < VQ) ob[row0 * VQ + v0 + 1]       = acc[mf][nf][1] + b0;
            if (v0 < VQ)     ob[(row0 + 8) * VQ + v0]     = acc[mf][nf][2] + b1;
            if (v0 + 1 < VQ) ob[(row0 + 8) * VQ + v0 + 1] = acc[mf][nf][3] + b1;
        }
    }
}

// Row softmax over g_S rows r<200; emit bf16x2-paired hi/lo probabilities.
__global__ __launch_bounds__(256)
void softmax_kernel() {
    const int wid = threadIdx.x >> 5, lane = threadIdx.x & 31;
    const int r = blockIdx.x * 8 + wid, b = blockIdx.y;
    const float* p = g_S + ((long long)b * RP + r) * NTOK;

    float2 v[25];
    float mx = -1e30f;
#pragma unroll
    for (int i = 0; i < 25; i++) {
        v[i] = *(const float2*)(p + i * 64 + lane * 2);
        mx = fmaxf(mx, fmaxf(v[i].x, v[i].y));
    }
#pragma unroll
    for (int o = 16; o; o >>= 1) mx = fmaxf(mx, __shfl_xor_sync(0xffffffffu, mx, o));
    float s = 0.f;
#pragma unroll
    for (int i = 0; i < 25; i++) {
        v[i].x = __expf(v[i].x - mx);
        v[i].y = __expf(v[i].y - mx);
        s += v[i].x + v[i].y;
    }
#pragma unroll
    for (int o = 16; o; o >>= 1) s += __shfl_xor_sync(0xffffffffu, s, o);
    const float inv = 1.f / s;

    bf* ph = g_Ph + ((long long)b * RP + r) * NTOK;
    bf* pl = g_Pl + ((long long)b * RP + r) * NTOK;
#pragma unroll
    for (int i = 0; i < 25; i++) {
        bf h0, l0, h1, l1;
        split_bf(v[i].x * inv, h0, l0);
        split_bf(v[i].y * inv, h1, l1);
        const int col = i * 64 + lane * 2;
        *(__nv_bfloat162*)(ph + col) = __nv_bfloat162(h0, h1);
        *(__nv_bfloat162*)(pl + col) = __nv_bfloat162(l0, l1);
    }
}

// ---------------------------------------------------------------
extern "C" void kernel_launch(void* const* d_in, const int* in_sizes, int n_in,
                              void* d_out, int out_size) {
    (void)in_sizes; (void)n_in; (void)out_size;
    const float* x_cls   = (const float*)d_in[0];
    const float* x_patch = (const float*)d_in[1];
    const float* q_w     = (const float*)d_in[2];
    const float* k_w     = (const float*)d_in[3];
    const float* v_w     = (const float*)d_in[4];
    const float* temp    = (const float*)d_in[5];
    const float* proj_w  = (const float*)d_in[6];
    const float* proj_b  = (const float*)d_in[7];
    float* out = (float*)d_out;

    const int SMEM1 = 2 * STG1;   // 102400
    const int SMEM2 = 2 * STG2;   // 98304
    const int SMEMF = 2 * STGF;   // 81920
    cudaFuncSetAttribute(mega1,     cudaFuncAttributeMaxDynamicSharedMemorySize, SMEM1);
    cudaFuncSetAttribute(gemm2_mma, cudaFuncAttributeMaxDynamicSharedMemorySize, SMEM2);
    cudaFuncSetAttribute(final_mma, cudaFuncAttributeMaxDynamicSharedMemorySize, SMEMF);

    mega1<<<BB + BB * NPB, 256, SMEM1>>>(x_cls, q_w, k_w, temp, proj_w, v_w, x_patch);
    softmax_kernel<<<dim3(RR / 8, BB), 256>>>();
    gemm2_mma<<<dim3(4, 2 * KSPL, BB), 256, SMEM2>>>();
    reduce_yt<<<dim3(RR, BB), 256>>>();
    final_mma<<<dim3(2, 1, BB), 256, SMEMF>>>(proj_b, out);
}